// round 11
// baseline (speedup 1.0000x reference)
#include <cuda_runtime.h>

// Problem constants: SCALE=64, B=4, P=S2=4096.
// Inputs (metadata order): corr_m (B,S2,S2) f32, gt_flow (B,2,64,64) f32,
//                          vis_mask (B,1,64,64) f32 [UNUSED],
//                          scale_ref (B,3,64,64) f32
// Output: concat(warp_smpl (B,3,64,64), warp_corr (B,3,64,64)) f32
//
// Two pixels per thread (aligned pair 2p, 2p+1): gt loads and output stores
// become vectorized float2 (LDG.64 / STG.64), halving their wavefront count;
// per-thread scattered-gather MLP doubles to 32. 128 blocks x 64 threads.
// Workload is otherwise launch-overhead bound (+-0.5us noise on identical
// code); this trims the sub-us body's instruction/wavefront count.

#define SC    64
#define S2    4096   // SC*SC
#define BATCH 4

__global__ __launch_bounds__(64)
void smpl_loss_pixel_kernel(const float* __restrict__ corr,
                            const float* __restrict__ gt,
                            const float* __restrict__ ref,
                            float* __restrict__ out)
{
    // 8192 threads, each handles pixels (2u, 2u+1) of batch b.
    const int u = blockIdx.x * blockDim.x + threadIdx.x;   // 0..8191
    const int b  = u >> 11;            // u / 2048
    const int p0 = (u & 2047) * 2;     // even pixel of the pair

    // --- Vectorized gt loads: float2 covers both pixels per channel ---
    const float2 gtx2 = *(const float2*)(gt + (b * 2 + 0) * S2 + p0);
    const float2 gty2 = *(const float2*)(gt + (b * 2 + 1) * S2 + p0);

    const float* __restrict__ rb0 = ref + (size_t)b * 3 * S2;
    const float* __restrict__ rb1 = rb0 + S2;
    const float* __restrict__ rb2 = rb0 + 2 * S2;

    float sA[3], qA[3];   // results for the two pixels
    float sB[3], qB[3];

#pragma unroll
    for (int px = 0; px < 2; px++) {
        const int p = p0 + px;
        const float gx = ((px ? gtx2.y : gtx2.x) + 1.0f) * ((SC - 1) * 0.5f);
        const float gy = ((px ? gty2.y : gty2.x) + 1.0f) * ((SC - 1) * 0.5f);
        const float fx = floorf(gx);
        const float fy = floorf(gy);

        const float r0 = fminf(fmaxf(fy,        0.0f), (float)(SC - 1));
        const float r1 = fminf(fmaxf(fy + 1.0f, 0.0f), (float)(SC - 1));
        const float c0 = fminf(fmaxf(fx,        0.0f), (float)(SC - 1));
        const float c1 = fminf(fmaxf(fx + 1.0f, 0.0f), (float)(SC - 1));

        int idx[4];
        idx[0] = (int)(r0 * (float)SC + c0);
        idx[1] = (int)(r0 * (float)SC + c1);
        idx[2] = (int)(r1 * (float)SC + c0);
        idx[3] = (int)(r1 * (float)SC + c1);

        const float wy0 = fy + 1.0f - gy;
        const float wy1 = gy - fy;
        const float wx0 = fx + 1.0f - gx;
        const float wx1 = gx - fx;
        float wgt[4];
        wgt[0] = wy0 * wx0;
        wgt[1] = wy0 * wx1;
        wgt[2] = wy1 * wx0;
        wgt[3] = wy1 * wx1;

        // Reference scatter-set semantics: on duplicate idx (only possible
        // under clipping) the LAST offset wins and contributes exactly once.
        bool keep[4];
#pragma unroll
        for (int i = 0; i < 4; i++) {
            keep[i] = true;
#pragma unroll
            for (int j = i + 1; j < 4; j++)
                if (idx[j] == idx[i]) keep[i] = false;
        }

        // All 16 scattered loads issued back-to-back (max MLP).
        const float* __restrict__ crow = corr + ((size_t)b * S2 + (size_t)p) * S2;
        float cv[4], rv0[4], rv1[4], rv2[4];
#pragma unroll
        for (int i = 0; i < 4; i++) {
            const int id = idx[i];
            cv[i]  = __ldg(crow + id);
            rv0[i] = __ldg(rb0 + id);
            rv1[i] = __ldg(rb1 + id);
            rv2[i] = __ldg(rb2 + id);
        }

        float s0 = 0.f, s1 = 0.f, s2 = 0.f;
        float q0 = 0.f, q1 = 0.f, q2 = 0.f;
#pragma unroll
        for (int i = 0; i < 4; i++) {
            if (!keep[i]) continue;
            const float wv = wgt[i];
            const float cc = cv[i];
            s0 = fmaf(wv, rv0[i], s0);
            s1 = fmaf(wv, rv1[i], s1);
            s2 = fmaf(wv, rv2[i], s2);
            q0 = fmaf(cc, rv0[i], q0);
            q1 = fmaf(cc, rv1[i], q1);
            q2 = fmaf(cc, rv2[i], q2);
        }

        if (px == 0) { sA[0]=s0; sA[1]=s1; sA[2]=s2; qA[0]=q0; qA[1]=q1; qA[2]=q2; }
        else         { sB[0]=s0; sB[1]=s1; sB[2]=s2; qB[0]=q0; qB[1]=q1; qB[2]=q2; }
    }

    // --- Vectorized output stores: float2 per (channel, tensor) ---
    const size_t base = ((size_t)b * 3) * S2 + (size_t)p0;
    float* __restrict__ oc = out + (size_t)BATCH * 3 * S2;
#pragma unroll
    for (int c = 0; c < 3; c++) {
        *(float2*)(out + base + (size_t)c * S2) = make_float2(sA[c], sB[c]);
        *(float2*)(oc  + base + (size_t)c * S2) = make_float2(qA[c], qB[c]);
    }
}

extern "C" void kernel_launch(void* const* d_in, const int* in_sizes, int n_in,
                              void* d_out, int out_size)
{
    const float* corr = (const float*)d_in[0];  // (4, 4096, 4096)
    const float* gt   = (const float*)d_in[1];  // (4, 2, 64, 64)
    // d_in[2] = vis_mask, unused
    const float* ref  = (const float*)d_in[3];  // (4, 3, 64, 64)
    float* out = (float*)d_out;                 // 2 * 4 * 3 * 4096 floats

    // 8192 threads x 2 pixels = 16384 pixels; 128 blocks x 64 threads.
    smpl_loss_pixel_kernel<<<128, 64>>>(corr, gt, ref, out);
}